// round 3
// baseline (speedup 1.0000x reference)
#include <cuda_runtime.h>
#include <cmath>

#define WLEN  512
#define SEG   16
#define VCOLS 16
#define VSTR  514   // column stride in vertical tile; 514 % 32 == 2 -> conflict-free staging

// Scratch (device globals: allocation-free rule)
__device__ float g_buf[4 * 32 * 512 * 512];   // 128 MB intermediate
__device__ float g_V1[4 * 512 * 512];         // exp(cc0 * D)
__device__ float g_V2[4 * 512 * 512];         // V1^2

__device__ __forceinline__ int SWZ(int w) { return w ^ (w >> 5); }

// Forward + backward domain-transform recursive filter on one line of 512
// elements held in smem (indexed through SWZ). vs holds V (vs[SWZ(0)] == 0).
// One warp per line; lane owns contiguous segment [16*lane, 16*lane+16).
__device__ __forceinline__ void scan_line(float* xs, const float* vs, int lane) {
    // ---------- forward:  x_i = v_i * x_{i-1} + (1-v_i) * e_i,  x_{-1} = 0
    float A = 1.f, B = 0.f;
#pragma unroll
    for (int j = 0; j < SEG; ++j) {
        int w = lane * SEG + j;
        float v = vs[SWZ(w)];
        float e = xs[SWZ(w)];
        B = fmaf(v, B - e, e);   // v*B + (1-v)*e
        A *= v;
    }
#pragma unroll
    for (int d = 1; d < 32; d <<= 1) {
        float Au = __shfl_up_sync(0xffffffffu, A, d);
        float Bu = __shfl_up_sync(0xffffffffu, B, d);
        if (lane >= d) { B = fmaf(A, Bu, B); A *= Au; }
    }
    float c = __shfl_up_sync(0xffffffffu, B, 1);
    float x = (lane == 0) ? 0.f : c;
#pragma unroll
    for (int j = 0; j < SEG; ++j) {
        int w = lane * SEG + j;
        float v = vs[SWZ(w)];
        float e = xs[SWZ(w)];
        x = fmaf(v, x - e, e);
        xs[SWZ(w)] = x;
    }
    __syncwarp();

    // ---------- backward: y_w = v_{w+1} * y_{w+1} + (1-v_{w+1}) * x_w, y_511 = x_511
    A = 1.f; B = 0.f;
#pragma unroll
    for (int j = 0; j < SEG; ++j) {
        int w = (WLEN - 1) - (lane * SEG + j);
        float v = (w == WLEN - 1) ? 0.f : vs[SWZ(w + 1)];
        float e = xs[SWZ(w)];
        B = fmaf(v, B - e, e);
        A *= v;
    }
#pragma unroll
    for (int d = 1; d < 32; d <<= 1) {
        float Au = __shfl_up_sync(0xffffffffu, A, d);
        float Bu = __shfl_up_sync(0xffffffffu, B, d);
        if (lane >= d) { B = fmaf(A, Bu, B); A *= Au; }
    }
    c = __shfl_up_sync(0xffffffffu, B, 1);
    x = (lane == 0) ? 0.f : c;
#pragma unroll
    for (int j = 0; j < SEG; ++j) {
        int w = (WLEN - 1) - (lane * SEG + j);
        float v = (w == WLEN - 1) ? 0.f : vs[SWZ(w + 1)];
        float e = xs[SWZ(w)];
        x = fmaf(v, x - e, e);
        xs[SWZ(w)] = x;
    }
    __syncwarp();
}

// ---------------------------------------------------------------------------
// V precompute: V1 = exp(cc0 * (1 + 150*edge)), V2 = V1^2  (sigma0 = 2*sigma1)
__global__ void __launch_bounds__(1024) vprep(const float* __restrict__ edge,
                                              float cc0, int n) {
    int i = blockIdx.x * blockDim.x + threadIdx.x;
    if (i < n) {
        float D  = fmaf(150.f, edge[i], 1.f);
        float v1 = expf(cc0 * D);
        g_V1[i] = v1;
        g_V2[i] = v1 * v1;
    }
}

// ---------------------------------------------------------------------------
// Horizontal pass: block = (b, h), 32 warps = 32 channels, scan along w.
// smem: 32*512 image tile + 512 shared V row.  2 blocks/SM.
__global__ void __launch_bounds__(1024) dt_h(const float* __restrict__ src,
                                             float* __restrict__ dst,
                                             const float* __restrict__ Vg) {
    extern __shared__ float sm[];
    float* timg = sm;                 // 32 * 512
    float* vs   = sm + 32 * WLEN;     // 512 (SWZ-indexed)

    int t = threadIdx.x, lane = t & 31, warp = t >> 5;
    int b = blockIdx.x >> 9, h = blockIdx.x & 511;

    if (t < WLEN) {
        float v = (t == 0) ? 0.f : Vg[((size_t)b * 512 + h) * 512 + t];
        vs[SWZ(t)] = v;
    }

    size_t base = (((size_t)b * 32 + warp) * 512 + h) * 512;
    const float4* s4 = reinterpret_cast<const float4*>(src + base);
    float* line = timg + warp * WLEN;
#pragma unroll
    for (int k = 0; k < 4; ++k) {
        float4 d = s4[k * 32 + lane];
        int w = (k * 32 + lane) * 4;
        line[SWZ(w)]     = d.x;
        line[SWZ(w + 1)] = d.y;
        line[SWZ(w + 2)] = d.z;
        line[SWZ(w + 3)] = d.w;
    }
    __syncthreads();

    scan_line(line, vs, lane);
    __syncthreads();

    float4* d4 = reinterpret_cast<float4*>(dst + base);
#pragma unroll
    for (int k = 0; k < 4; ++k) {
        int w = (k * 32 + lane) * 4;
        float4 o;
        o.x = line[SWZ(w)];
        o.y = line[SWZ(w + 1)];
        o.z = line[SWZ(w + 2)];
        o.w = line[SWZ(w + 3)];
        d4[k * 32 + lane] = o;
    }
}

// ---------------------------------------------------------------------------
// Vertical pass: block = (b, c, 16-column group), 16 warps = 16 columns,
// scan along h. smem: img tile [16 cols][514] + V tile [16 cols][514].
// 65.8 KB smem, 512 threads -> 3 blocks/SM (scan compute overlaps staging).
__global__ void __launch_bounds__(512) dt_v(const float* __restrict__ src,
                                            float* __restrict__ dst,
                                            const float* __restrict__ Vg) {
    extern __shared__ float sm[];
    float* timg = sm;                  // 16 * 514
    float* tv   = sm + VCOLS * VSTR;   // 16 * 514

    int t = threadIdx.x, lane = t & 31, warp = t >> 5;
    int wg = blockIdx.x & 31, c = (blockIdx.x >> 5) & 31, b = blockIdx.x >> 10;
    int w0 = wg * VCOLS;
    int f = t & 3, row = t >> 2;       // f: float4 slot along w, row: h sub-row (0..127)

    const float* sbase = src + (((size_t)b * 32 + c) * 512) * 512 + w0;
    const float* vbase = Vg + ((size_t)b * 512) * 512 + w0;

#pragma unroll
    for (int k = 0; k < 4; ++k) {
        int h = k * 128 + row;
        float4 d  = *reinterpret_cast<const float4*>(sbase + (size_t)h * 512 + f * 4);
        float4 vv = *reinterpret_cast<const float4*>(vbase + (size_t)h * 512 + f * 4);
        if (h == 0) { vv.x = 0.f; vv.y = 0.f; vv.z = 0.f; vv.w = 0.f; }
        int s = SWZ(h);
        int col = f * 4;
        timg[(col    ) * VSTR + s] = d.x;
        timg[(col + 1) * VSTR + s] = d.y;
        timg[(col + 2) * VSTR + s] = d.z;
        timg[(col + 3) * VSTR + s] = d.w;
        tv  [(col    ) * VSTR + s] = vv.x;
        tv  [(col + 1) * VSTR + s] = vv.y;
        tv  [(col + 2) * VSTR + s] = vv.z;
        tv  [(col + 3) * VSTR + s] = vv.w;
    }
    __syncthreads();

    scan_line(timg + warp * VSTR, tv + warp * VSTR, lane);
    __syncthreads();

    float* dbase = dst + (((size_t)b * 32 + c) * 512) * 512 + w0;
#pragma unroll
    for (int k = 0; k < 4; ++k) {
        int h = k * 128 + row;
        int s = SWZ(h);
        int col = f * 4;
        float4 o;
        o.x = timg[(col    ) * VSTR + s];
        o.y = timg[(col + 1) * VSTR + s];
        o.z = timg[(col + 2) * VSTR + s];
        o.w = timg[(col + 3) * VSTR + s];
        *reinterpret_cast<float4*>(dbase + (size_t)h * 512 + f * 4) = o;
    }
}

// ---------------------------------------------------------------------------
extern "C" void kernel_launch(void* const* d_in, const int* in_sizes, int n_in,
                              void* d_out, int out_size) {
    const float* img  = (const float*)d_in[0];
    const float* edge = (const float*)d_in[1];
    // defensive: identify by size (img = 33.5M, edge = 1M)
    if (n_in >= 2 && in_sizes[0] == (1 << 20)) {
        const float* tmp = img; img = edge; edge = tmp;
    }
    float* out = (float*)d_out;

    float *buf, *V1, *V2;
    cudaGetSymbolAddress((void**)&buf, g_buf);
    cudaGetSymbolAddress((void**)&V1, g_V1);
    cudaGetSymbolAddress((void**)&V2, g_V2);

    const int SMEM_H = (32 * WLEN + WLEN) * (int)sizeof(float);     // 67584 B
    const int SMEM_V = 2 * VCOLS * VSTR * (int)sizeof(float);       // 65792 B
    cudaFuncSetAttribute(dt_h, cudaFuncAttributeMaxDynamicSharedMemorySize, SMEM_H);
    cudaFuncSetAttribute(dt_v, cudaFuncAttributeMaxDynamicSharedMemorySize, SMEM_V);

    // sigma_0 = 60*sqrt(3)*2/sqrt(15);  cc0 = -sqrt(2)/sigma_0;  sigma_1 = sigma_0/2
    double sigma0 = 60.0 * 1.7320508075688772 * 2.0 / sqrt(15.0);
    float cc0 = (float)(-1.4142135623730951 / sigma0);

    vprep<<<1024, 1024>>>(edge, cc0, 1 << 20);
    dt_h<<<2048, 1024, SMEM_H>>>(img, buf, V1);   // iter 0, horizontal
    dt_v<<<4096,  512, SMEM_V>>>(buf, buf, V1);   // iter 0, vertical (in place)
    dt_h<<<2048, 1024, SMEM_H>>>(buf, buf, V2);   // iter 1, horizontal (in place)
    dt_v<<<4096,  512, SMEM_V>>>(buf, out, V2);   // iter 1, vertical -> output
}